// round 16
// baseline (speedup 1.0000x reference)
#include <cuda_runtime.h>
#include <cuda_bf16.h>
#include <cstdint>
#include <math_constants.h>

// Problem constants
#define BB 16
#define CC 8
#define TT 4096
#define KK 64
#define LL 128
#define TP (TT - LL + 1)        // 3969 valid sliding positions
#define TCHUNK 224              // t' per CTA (288 CTAs: balanced on 148 SMs)
#define NCHUNK 18               // 18*224 = 4032 >= 3969
#define NSTEP 8                 // 128 / 16 k per bf16 mma
#define NMT 14                  // m-tiles per CTA (224 / 16)
#define NDIAG 21                // u = m + s in [0, 13+7]
#define XLEN (TCHUNK + LL)      // 352
#define SSTR 132                // padded S row stride (floats) in smem

typedef unsigned int u32;

// Cross-CTA scratch: per-(b,chunk) partial mins + arrival counters.
__device__ float gPart[BB * NCHUNK * KK];   // plain STG, no init needed
__device__ u32   gCnt[BB];                  // monotonic; (old % NCHUNK) picks last

__device__ __forceinline__ u32 pack_bf16(float a, float b) {
    __nv_bfloat162 h = __floats2bfloat162_rn(a, b);
    return *(u32*)&h;
}

__device__ __forceinline__ u32 smem_u32(const void* p) {
    u32 a;
    asm("{ .reg .u64 t; cvta.to.shared.u64 t, %1; cvt.u32.u64 %0, t; }" : "=r"(a) : "l"(p));
    return a;
}

__device__ __forceinline__ void cp16(u32 saddr, const void* gaddr) {
    asm volatile("cp.async.cg.shared.global [%0], [%1], 16;" :: "r"(saddr), "l"(gaddr));
}

__device__ __forceinline__ void mma_bf16(float* c, u32 a0, u32 a1, u32 a2, u32 a3,
                                         u32 b0, u32 b1) {
    asm volatile(
        "mma.sync.aligned.m16n8k16.row.col.f32.bf16.bf16.f32 "
        "{%0,%1,%2,%3}, {%4,%5,%6,%7}, {%8,%9}, {%0,%1,%2,%3};"
        : "+f"(c[0]), "+f"(c[1]), "+f"(c[2]), "+f"(c[3])
        : "r"(a0), "r"(a1), "r"(a2), "r"(a3), "r"(b0), "r"(b1));
}

__global__ __launch_bounds__(256, 2)
void shapelet_fused_kernel(const float* __restrict__ X,
                           const float* __restrict__ S,
                           float* __restrict__ out) {
    __shared__ float sS[KK * SSTR];        // S copy, padded rows (33.8 KB)
    __shared__ float xs[XLEN + 4];         // channel-sum (f32); zero pad
    __shared__ float xq[XLEN];             // channel-sum of x^2
    __shared__ u32   ea[180];              // bf16x2(xs[2j], xs[2j+1])
    __shared__ u32   oa[180];              // bf16x2(xs[2j+1], xs[2j+2])
    __shared__ float pscan[XLEN];          // per-32-seg inclusive scans of xq
    __shared__ float segt[11];             // segment totals
    __shared__ float ws[TCHUNK];           // window sums (+inf past TP)
    __shared__ int   lastFlag;

    const int tid  = threadIdx.x;
    const int wid  = tid >> 5;             // warp = n-tile (8 warps, 8 nt)
    const int lane = tid & 31;
    const int g    = lane >> 2;            // groupID 0..7
    const int t    = lane & 3;             // threadID_in_group 0..3
    const int b    = blockIdx.y;
    const int chunk = blockIdx.x;
    const int tbase = chunk * TCHUNK;

    // ---- Phase 0: cp.async S -> smem (32 KB data, padded rows) ----
    {
        const u32 sbase = smem_u32(sS);
        #pragma unroll
        for (int i = 0; i < 8; i++) {
            int c = tid + i * 256;         // chunk of 16B; 2048 total
            int row = c >> 5;              // 32 chunks per 512B row
            int col = c & 31;
            cp16(sbase + row * (SSTR * 4) + col * 16,
                 (const char*)S + row * 512 + col * 16);
        }
        asm volatile("cp.async.commit_group;" ::: "memory");
    }

    // ---- Phase 1: X channel sums for t in [tbase, tbase+352) ----
    for (int j = tid; j < XLEN; j += 256) {
        int tg = tbase + j;
        float sm = 0.f, sq = 0.f;
        if (tg < TT) {
            #pragma unroll
            for (int c = 0; c < CC; c++) {
                float v = X[((b * CC + c) << 12) + tg];
                sm += v; sq += v * v;
            }
        }
        xs[j] = sm; xq[j] = sq;
    }
    if (tid < 4) xs[XLEN + tid] = 0.f;
    asm volatile("cp.async.wait_group 0;" ::: "memory");
    __syncthreads();

    // ---- Phase 1.5: pack B fragments from smem S ----
    // Lane covers row = 8*wid + g, cols {16s+2t,+1, 16s+8+2t,+1 : s=0..7}.
    uint2 Bv[NSTEP];
    {
        const float2* Sr = (const float2*)(sS + (wid * 8 + g) * SSTR);
        #pragma unroll
        for (int s = 0; s < NSTEP; s++) {
            float2 p = Sr[s * 8 + t];
            float2 q = Sr[s * 8 + 4 + t];
            Bv[s].x = pack_bf16(p.x, p.y);
            Bv[s].y = pack_bf16(q.x, q.y);
        }
    }

    // ---- Parity-aligned bf16 pair arrays for A fragments ----
    if (tid < 177) {
        float x0 = xs[2 * tid], x1 = xs[2 * tid + 1], x2 = xs[2 * tid + 2];
        ea[tid] = pack_bf16(x0, x1);
        oa[tid] = pack_bf16(x1, x2);
    }

    // ---- Segmented scan of xq (11 segments of 32) ----
    for (int seg = wid; seg < 11; seg += 8) {
        float v = xq[seg * 32 + lane];
        #pragma unroll
        for (int o = 1; o < 32; o <<= 1) {
            float u = __shfl_up_sync(0xffffffffu, v, o);
            if (lane >= o) v += u;
        }
        pscan[seg * 32 + lane] = v;
        if (lane == 31) segt[seg] = v;
    }
    __syncthreads();

    // ---- ws[t'] = sum_{i=t'}^{t'+127} xq[i], via segment decomposition ----
    if (tid < TCHUNK) {
        int q = tid >> 5, r = tid & 31;
        float suf  = segt[q] - (pscan[tid] - xq[tid]);
        float mid  = segt[q + 1] + segt[q + 2] + segt[q + 3];
        float head = (r == 0) ? 0.f : pscan[(q + 4) * 32 + r - 1];
        float w = suf + mid + head;
        ws[tid] = (tbase + tid < TP) ? w : CUDART_INF_F;
    }
    __syncthreads();

    // ---- Main: diagonal-order GEMM. Warp owns nt=wid, 14 m-tiles. ----
    // A[r][c] = xs[r + c] (Toeplitz). frag(m,s) = (Av[2u], Av[2u+1], Av[2u+1],
    // Av[2u+2]) with u = m+s, Av[j] = ap[j00 + 4j].
    const u32* ap = (g & 1) ? oa : ea;
    const int j00 = (g + 2 * t) >> 1;

    float acc[NMT][4];
    #pragma unroll
    for (int m = 0; m < NMT; m++)
        #pragma unroll
        for (int j = 0; j < 4; j++)
            acc[m][j] = 0.f;

    u32 A0 = ap[j00];          // Av[0]
    u32 A1 = ap[j00 + 4];      // Av[1]
    #pragma unroll
    for (int u = 0; u < NDIAG; u++) {
        u32 A2 = ap[j00 + 8 * u + 8];      // Av[2u+2]
        #pragma unroll
        for (int s = 0; s < NSTEP; s++) {
            const int m = u - s;
            if (m >= 0 && m < NMT)
                mma_bf16(acc[m], A0, A1, A1, A2, Bv[s].x, Bv[s].y);
        }
        if (u < NDIAG - 1) {
            A0 = A2;
            A1 = ap[j00 + 8 * u + 12];     // Av[2u+3]
        }
    }

    // ---- Epilogue: dist = ws - 2*corr, per-warp min over 224 rows ----
    // Thread covers k0 = 8*wid + 2t, k1 = k0+1; rows 16m+g and 16m+g+8.
    float m0 = CUDART_INF_F, m1 = CUDART_INF_F;
    #pragma unroll
    for (int m = 0; m < NMT; m++) {
        float w0 = ws[16 * m + g];
        float w1 = ws[16 * m + g + 8];
        m0 = fminf(m0, fminf(fmaf(-2.f, acc[m][0], w0), fmaf(-2.f, acc[m][2], w1)));
        m1 = fminf(m1, fminf(fmaf(-2.f, acc[m][1], w0), fmaf(-2.f, acc[m][3], w1)));
    }
    #pragma unroll
    for (int o = 4; o <= 16; o <<= 1) {
        m0 = fminf(m0, __shfl_xor_sync(0xffffffffu, m0, o));
        m1 = fminf(m1, __shfl_xor_sync(0xffffffffu, m1, o));
    }
    if (g == 0) {
        int k0 = wid * 8 + 2 * t;
        float* gp = gPart + (b * NCHUNK + chunk) * KK;
        gp[k0]     = m0;
        gp[k0 + 1] = m1;
    }

    // ---- Last-CTA-per-b reduction (threadFenceReduction pattern) ----
    __threadfence();
    __syncthreads();
    if (tid == 0) {
        u32 old = atomicAdd(&gCnt[b], 1u);
        lastFlag = ((old % NCHUNK) == (NCHUNK - 1)) ? 1 : 0;
    }
    __syncthreads();
    if (lastFlag && tid < KK) {
        // shapelet norm for k = tid from this CTA's smem S copy
        const float4* Sk = (const float4*)(sS + tid * SSTR);
        float ns = 0.f;
        #pragma unroll
        for (int i = 0; i < LL / 4; i++) {
            float4 v = Sk[i];
            ns += v.x * v.x + v.y * v.y + v.z * v.z + v.w * v.w;
        }
        float mn = CUDART_INF_F;
        const float* gp = gPart + b * NCHUNK * KK + tid;
        #pragma unroll 6
        for (int c = 0; c < NCHUNK; c++)
            mn = fminf(mn, __ldcg(gp + c * KK));
        out[b * KK + tid] = mn + (float)CC * ns;
    }
}

extern "C" void kernel_launch(void* const* d_in, const int* in_sizes, int n_in,
                              void* d_out, int out_size) {
    const float* X = (const float*)d_in[0];   // (16, 8, 4096) f32
    const float* S = (const float*)d_in[1];   // (64, 128) f32
    float* out = (float*)d_out;               // (16, 64) f32

    dim3 grid(NCHUNK, BB);
    shapelet_fused_kernel<<<grid, 256>>>(X, S, out);
}

// round 17
// speedup vs baseline: 1.2773x; 1.2773x over previous
#include <cuda_runtime.h>
#include <cuda_bf16.h>
#include <cstdint>
#include <math_constants.h>

// Problem constants
#define BB 16
#define CC 8
#define TT 4096
#define KK 64
#define LL 128
#define TP (TT - LL + 1)        // 3969 valid sliding positions
#define TCHUNK 448              // t' per CTA (one 512-thread CTA per SM)
#define NCHUNK 9                // 9*448 = 4032 >= 3969
#define NSTEP 8                 // 128 / 16 k per bf16 mma
#define NMT 14                  // m-tiles per warp (224 rows / 16)
#define NDIAG 21                // u = m + s in [0, 13+7]
#define XLEN (TCHUNK + LL)      // 576
#define NSEG (XLEN / 32)        // 18 scan segments

typedef unsigned int u32;

// Pre-packed B fragments [step][nt][lane] = (b0,b1) and shapelet norms
__device__ uint2 gB[NSTEP * 8 * 32];    // 16 KB
__device__ float gOffs[KK];

__device__ __forceinline__ u32 pack_bf16(float a, float b) {
    __nv_bfloat162 h = __floats2bfloat162_rn(a, b);
    return *(u32*)&h;
}

__device__ __forceinline__ void mma_bf16(float* c, u32 a0, u32 a1, u32 a2, u32 a3,
                                         u32 b0, u32 b1) {
    asm volatile(
        "mma.sync.aligned.m16n8k16.row.col.f32.bf16.bf16.f32 "
        "{%0,%1,%2,%3}, {%4,%5,%6,%7}, {%8,%9}, {%0,%1,%2,%3};"
        : "+f"(c[0]), "+f"(c[1]), "+f"(c[2]), "+f"(c[3])
        : "r"(a0), "r"(a1), "r"(a2), "r"(a3), "r"(b0), "r"(b1));
}

// Prep: pack B fragments, shapelet norms, init out. grid = 8 CTAs x 256.
__global__ void prep_kernel(const float* __restrict__ S, int* __restrict__ out) {
    const int tid  = threadIdx.x;
    const int wid  = tid >> 5;
    const int lane = tid & 31;
    const int g    = lane >> 2;
    const int t    = lane & 3;
    const int cta  = blockIdx.x;         // 0..7

    // B fragments: this CTA covers nt = cta; warp wid covers step s = wid.
    {
        int nt = cta, s = wid;
        int row = nt * 8 + g;
        const float2* Sr = (const float2*)(S + row * LL);
        float2 p = Sr[s * 8 + t];
        float2 q = Sr[s * 8 + 4 + t];
        uint2 v;
        v.x = pack_bf16(p.x, p.y);
        v.y = pack_bf16(q.x, q.y);
        gB[s * 256 + nt * 32 + lane] = v;
    }

    // Norms: warp wid computes row r = cta*8 + wid
    {
        int r = cta * 8 + wid;
        const float4* Sr = (const float4*)(S + r * LL);
        float4 v = Sr[lane];
        float ns = v.x * v.x + v.y * v.y + v.z * v.z + v.w * v.w;
        #pragma unroll
        for (int o = 16; o > 0; o >>= 1)
            ns += __shfl_xor_sync(0xffffffffu, ns, o);
        if (lane == 0) gOffs[r] = (float)CC * ns;
    }

    // Init out: 1024 ints / 8 CTAs = 128 each
    if (tid < 128) out[cta * 128 + tid] = 0x7F800000;
}

__global__ __launch_bounds__(512, 1)
void shapelet_bf16_kernel(const float* __restrict__ X,
                          float* __restrict__ out) {
    __shared__ float xs[XLEN + 4];         // channel-sum (f32); zero pad
    __shared__ float xq[XLEN];             // channel-sum of x^2
    __shared__ u32   ea[XLEN / 2 + 4];     // bf16x2(xs[2j], xs[2j+1])
    __shared__ u32   oa[XLEN / 2 + 4];     // bf16x2(xs[2j+1], xs[2j+2])
    __shared__ float pscan[XLEN];          // per-32-seg inclusive scans of xq
    __shared__ float segt[NSEG];           // segment totals
    __shared__ float ws[TCHUNK];           // window sums (+inf past TP)

    const int tid  = threadIdx.x;
    const int wid  = tid >> 5;             // 16 warps
    const int lane = tid & 31;
    const int g    = lane >> 2;            // groupID 0..7
    const int t    = lane & 3;             // threadID_in_group 0..3
    const int nt   = wid >> 1;             // n-tile 0..7 (2 warps each)
    const int mh   = wid & 1;              // m-half: rows [224*mh, 224*mh+224)
    const int b    = blockIdx.y;
    const int tbase = blockIdx.x * TCHUNK;

    // ---- Early LDGs: B fragments for this warp's nt (L2-resident) + norms ----
    uint2 Bv[NSTEP];
    #pragma unroll
    for (int s = 0; s < NSTEP; s++) Bv[s] = gB[s * 256 + nt * 32 + lane];
    const float offs0 = gOffs[nt * 8 + 2 * t];
    const float offs1 = gOffs[nt * 8 + 2 * t + 1];

    // ---- Prologue: channel sums for t in [tbase, tbase+576) ----
    for (int j = tid; j < XLEN; j += 512) {
        int tg = tbase + j;
        float sm = 0.f, sq = 0.f;
        if (tg < TT) {
            #pragma unroll
            for (int c = 0; c < CC; c++) {
                float v = X[((b * CC + c) << 12) + tg];
                sm += v; sq += v * v;
            }
        }
        xs[j] = sm; xq[j] = sq;
    }
    if (tid < 4) xs[XLEN + tid] = 0.f;
    __syncthreads();

    // ---- Parity-aligned bf16 pair arrays for A fragments ----
    if (tid < XLEN / 2 + 1) {
        float x0 = xs[2 * tid], x1 = xs[2 * tid + 1], x2 = xs[2 * tid + 2];
        ea[tid] = pack_bf16(x0, x1);
        oa[tid] = pack_bf16(x1, x2);
    }

    // ---- Segmented scan of xq (18 segments of 32) ----
    for (int seg = wid; seg < NSEG; seg += 16) {
        float v = xq[seg * 32 + lane];
        #pragma unroll
        for (int o = 1; o < 32; o <<= 1) {
            float u = __shfl_up_sync(0xffffffffu, v, o);
            if (lane >= o) v += u;
        }
        pscan[seg * 32 + lane] = v;
        if (lane == 31) segt[seg] = v;
    }
    __syncthreads();

    // ---- ws[t'] = sum_{i=t'}^{t'+127} xq[i], via segment decomposition ----
    if (tid < TCHUNK) {
        int q = tid >> 5, r = tid & 31;
        float suf  = segt[q] - (pscan[tid] - xq[tid]);
        float mid  = segt[q + 1] + segt[q + 2] + segt[q + 3];
        float head = (r == 0) ? 0.f : pscan[(q + 4) * 32 + r - 1];
        float w = suf + mid + head;
        ws[tid] = (tbase + tid < TP) ? w : CUDART_INF_F;
    }
    __syncthreads();

    // ---- Main: diagonal-order GEMM. Warp owns nt, rows [224*mh, +224). ----
    // A[r][c] = xs[r + c] (Toeplitz). frag(m,s) = (Av[2u], Av[2u+1], Av[2u+1],
    // Av[2u+2]) with u = m+s, Av[j] = ap[j00 + 4j]. Row offset 224*mh = 112 pairs.
    const u32* ap = (g & 1) ? oa : ea;
    const int j00 = mh * 112 + ((g + 2 * t) >> 1);

    float acc[NMT][4];
    #pragma unroll
    for (int m = 0; m < NMT; m++)
        #pragma unroll
        for (int j = 0; j < 4; j++)
            acc[m][j] = 0.f;

    u32 A0 = ap[j00];          // Av[0]
    u32 A1 = ap[j00 + 4];      // Av[1]
    #pragma unroll
    for (int u = 0; u < NDIAG; u++) {
        u32 A2 = ap[j00 + 8 * u + 8];      // Av[2u+2]
        #pragma unroll
        for (int s = 0; s < NSTEP; s++) {
            const int m = u - s;
            if (m >= 0 && m < NMT)
                mma_bf16(acc[m], A0, A1, A1, A2, Bv[s].x, Bv[s].y);
        }
        if (u < NDIAG - 1) {
            A0 = A2;
            A1 = ap[j00 + 8 * u + 12];     // Av[2u+3]
        }
    }

    // ---- Epilogue: dist = ws - 2*corr, min over this warp's 224 rows ----
    // Thread covers k0 = 8*nt + 2t, k1 = k0+1; rows 224*mh + 16m + g (+8).
    const int rbase = mh * 224;
    float m0 = CUDART_INF_F, m1 = CUDART_INF_F;
    #pragma unroll
    for (int m = 0; m < NMT; m++) {
        float w0 = ws[rbase + 16 * m + g];
        float w1 = ws[rbase + 16 * m + g + 8];
        m0 = fminf(m0, fminf(fmaf(-2.f, acc[m][0], w0), fmaf(-2.f, acc[m][2], w1)));
        m1 = fminf(m1, fminf(fmaf(-2.f, acc[m][1], w0), fmaf(-2.f, acc[m][3], w1)));
    }
    // reduce across g (lane bits 2..4); lanes 0..3 (g==0) hold results
    #pragma unroll
    for (int o = 4; o <= 16; o <<= 1) {
        m0 = fminf(m0, __shfl_xor_sync(0xffffffffu, m0, o));
        m1 = fminf(m1, __shfl_xor_sync(0xffffffffu, m1, o));
    }
    if (g == 0) {
        int k0 = nt * 8 + 2 * t;
        atomicMin((int*)&out[b * KK + k0],     __float_as_int(m0 + offs0));
        atomicMin((int*)&out[b * KK + k0 + 1], __float_as_int(m1 + offs1));
    }
}

extern "C" void kernel_launch(void* const* d_in, const int* in_sizes, int n_in,
                              void* d_out, int out_size) {
    const float* X = (const float*)d_in[0];   // (16, 8, 4096) f32
    const float* S = (const float*)d_in[1];   // (64, 128) f32
    float* out = (float*)d_out;               // (16, 64) f32

    prep_kernel<<<8, 256>>>(S, (int*)out);
    dim3 grid(NCHUNK, BB);
    shapelet_bf16_kernel<<<grid, 512>>>(X, out);
}